// round 6
// baseline (speedup 1.0000x reference)
#include <cuda_runtime.h>
#include <math.h>

#define NBATCH 64
#define NSTEP  1024
#define NIN    256
#define NH     512

#define WROW 516  // padded k-stride (floats): (4*jl + k) % 32 distinct per LDS.128 phase
#define SMEM_FLOATS (3*32*WROW + 8*768)
#define SMEM_BYTES  (SMEM_FLOATS*4)

typedef unsigned long long u64;

// packed fp32x2 FMA: d = a*b + c (elementwise on 2 packed floats) — SASS FFMA2
#define FMA2(acc, a, b) asm("fma.rn.f32x2 %0, %1, %2, %0;" : "+l"(acc) : "l"(a), "l"(b))
#define DUP2(r, x)      asm("mov.b64 %0, {%1, %1};" : "=l"(r) : "f"(x))
#define UNPACK2(lo, hi, v) asm("mov.b64 {%0, %1}, %2;" : "=f"(lo), "=f"(hi) : "l"(v))

// scratch: input projections x[gate][b][t][j], double-buffered h, per-group flags
__device__ float    g_x[(size_t)3*NBATCH*NSTEP*NH];   // ~403 MB
__device__ float    g_h[2*NBATCH*NH];
__device__ unsigned g_flags[128];

__device__ __forceinline__ unsigned ld_acq(const unsigned* p) {
  unsigned v;
  asm volatile("ld.global.acquire.gpu.b32 %0, [%1];" : "=r"(v) : "l"(p) : "memory");
  return v;
}
__device__ __forceinline__ void st_rel(unsigned* p, unsigned v) {
  asm volatile("st.global.release.gpu.b32 [%0], %1;" :: "l"(p), "r"(v) : "memory");
}

// ---------------- input projection GEMM: C[g][m][n] = A[m][:] . W_g[n][:] + b_g[n] ----------------
__global__ void __launch_bounds__(256) xproj_kernel(
    const float* __restrict__ A,
    const float* __restrict__ w0, const float* __restrict__ w1, const float* __restrict__ w2,
    const float* __restrict__ b0, const float* __restrict__ b1, const float* __restrict__ b2)
{
  __shared__ float As[32][68];
  __shared__ float Bs[32][68];

  int tid = threadIdx.x;
  if (blockIdx.x == 0 && blockIdx.y == 0 && blockIdx.z == 0 && tid < 128)
    g_flags[tid] = 0u;

  int g = blockIdx.z;
  const float* W    = (g==0) ? w0 : ((g==1) ? w1 : w2);
  const float* bias = (g==0) ? b0 : ((g==1) ? b1 : b2);
  float* C = g_x + (size_t)g * (size_t)(NBATCH*NSTEP) * NH;

  int m0 = blockIdx.y * 64;
  int n0 = blockIdx.x * 64;
  int tx = tid & 15, ty = tid >> 4;
  int lr = tid >> 3;
  int lc = (tid & 7) * 4;

  u64 acc2[4][2] = {};

  for (int k0 = 0; k0 < NIN; k0 += 32) {
    float4 a0 = *(const float4*)(A + (size_t)(m0+lr   )*NIN + k0 + lc);
    float4 a1 = *(const float4*)(A + (size_t)(m0+lr+32)*NIN + k0 + lc);
    float4 v0 = *(const float4*)(W + (size_t)(n0+lr   )*NIN + k0 + lc);
    float4 v1 = *(const float4*)(W + (size_t)(n0+lr+32)*NIN + k0 + lc);
    __syncthreads();
    As[lc+0][lr] = a0.x; As[lc+1][lr] = a0.y; As[lc+2][lr] = a0.z; As[lc+3][lr] = a0.w;
    As[lc+0][lr+32] = a1.x; As[lc+1][lr+32] = a1.y; As[lc+2][lr+32] = a1.z; As[lc+3][lr+32] = a1.w;
    Bs[lc+0][lr] = v0.x; Bs[lc+1][lr] = v0.y; Bs[lc+2][lr] = v0.z; Bs[lc+3][lr] = v0.w;
    Bs[lc+0][lr+32] = v1.x; Bs[lc+1][lr+32] = v1.y; Bs[lc+2][lr+32] = v1.z; Bs[lc+3][lr+32] = v1.w;
    __syncthreads();
    #pragma unroll
    for (int kk = 0; kk < 32; kk++) {
      float4 av = *(const float4*)(&As[kk][ty*4]);
      ulonglong2 bp = *(const ulonglong2*)(&Bs[kk][tx*4]);
      u64 d0, d1, d2, d3;
      DUP2(d0, av.x); DUP2(d1, av.y); DUP2(d2, av.z); DUP2(d3, av.w);
      FMA2(acc2[0][0], d0, bp.x); FMA2(acc2[0][1], d0, bp.y);
      FMA2(acc2[1][0], d1, bp.x); FMA2(acc2[1][1], d1, bp.y);
      FMA2(acc2[2][0], d2, bp.x); FMA2(acc2[2][1], d2, bp.y);
      FMA2(acc2[3][0], d3, bp.x); FMA2(acc2[3][1], d3, bp.y);
    }
  }

  float4 bv = *(const float4*)(bias + n0 + tx*4);
  #pragma unroll
  for (int i = 0; i < 4; i++) {
    int row = m0 + ty*4 + i;
    float c0, c1, c2, c3;
    UNPACK2(c0, c1, acc2[i][0]);
    UNPACK2(c2, c3, acc2[i][1]);
    float4 o;
    o.x = c0 + bv.x; o.y = c1 + bv.y;
    o.z = c2 + bv.z; o.w = c3 + bv.w;
    *(float4*)(C + (size_t)row*NH + n0 + tx*4) = o;
  }
}

// ---------------- persistent GRU recurrence (warp-decoupled handshake) ----------------
// 128 CTAs: blockIdx = bgrp(8)*16 + jt(16). 512 threads, warp r = tid>>5 (k-split 16).
// Warp r only consumes h-chunk [r*32, r*32+32), produced by exactly CTA (bgrp, r):
// it polls ONLY that producer's flag and stages only its own 1KB chunk — producer
// jitter delays one warp, overlapped by the other 15 warps' matvec. CTA-wide rejoin
// happens at the reduce barrier. h_old is carried in registers across steps.
__global__ void __launch_bounds__(512, 1) gru_rec(
    const float* __restrict__ h0,
    const float* __restrict__ w_hr, const float* __restrict__ w_hz, const float* __restrict__ w_hn,
    const float* __restrict__ b_hr, const float* __restrict__ b_hz, const float* __restrict__ b_hn,
    float* __restrict__ out, int write_hlast)
{
  extern __shared__ float sm[];
  float* wsm  = sm;                    // [3][32][WROW]  (~193.5 KB)
  float* un   = sm + 3*32*WROW;        // union: hsm [8][512] (16KB) / part [8][768] (24KB)
  float* hsm  = un;
  float* part = un;

  int tid  = threadIdx.x;
  int r    = tid >> 5;                 // 0..15 k-split == warp index == source chunk
  int jl   = tid & 31;
  int bgrp = blockIdx.x >> 4;
  int jt   = blockIdx.x & 15;
  int j    = jt*32 + jl;
  int k0   = r*32;

  // load recurrent weights for this j-slice into smem: wsm[g][jl][k]
  {
    const float* srcs[3] = {w_hr, w_hz, w_hn};
    #pragma unroll
    for (int g = 0; g < 3; g++) {
      const float* wsrc = srcs[g] + (size_t)j*NH;
      float* wdst = wsm + (g*32 + jl)*WROW;
      #pragma unroll
      for (int kk = 0; kk < 32; kk += 4)
        *(float4*)(wdst + k0 + kk) = *(const float4*)(wsrc + k0 + kk);
    }
  }
  float bhr = b_hr[j], bhz = b_hz[j], bhn = b_hn[j];
  int bb = bgrp*8 + r;                 // epilogue batch (valid for r<8)

  const float* xr_p = g_x + (size_t)bb*NSTEP*NH + j;
  const float* xz_p = xr_p + (size_t)NBATCH*NSTEP*NH;
  const float* xn_p = xz_p + (size_t)NBATCH*NSTEP*NH;
  float* out_p   = out + (size_t)bb*NSTEP*NH + j;
  float* hlast_p = out + (size_t)NBATCH*NSTEP*NH + (size_t)bb*NH + j;

  unsigned* myflag = g_flags + bgrp*16 + jt;            // what THIS CTA releases
  const unsigned* myprod = g_flags + bgrp*16 + r;       // what warp r waits on

  const float* wr = wsm + (0*32 + jl)*WROW;
  const float* wz = wsm + (1*32 + jl)*WROW;
  const float* wn = wsm + (2*32 + jl)*WROW;

  // register-resident previous h for the epilogue thread's (bb, j)
  float hprev = (r < 8) ? h0[(size_t)bb*NH + j] : 0.f;

  // staging map: warp r stages 64 float4 = cols [r*8, r*8+8) of the [8][128]-float4 grid
  int sb = jl >> 2;                    // batch 0..7
  int sc = jl & 3;                     // col pair base
  const float4* h0s = (const float4*)(h0 + (size_t)bgrp*8*NH);
  float4* hsm4 = (float4*)hsm;

  __syncthreads();   // weights visible

  #pragma unroll 1
  for (int t = 0; t < NSTEP; t++) {
    // prefetch this step's input-projection contributions (epilogue threads only)
    float xr = 0.f, xz = 0.f, xn = 0.f;
    if (r < 8) {
      xr = __ldcs(xr_p + (size_t)t*NH);
      xz = __ldcs(xz_p + (size_t)t*NH);
      xn = __ldcs(xn_p + (size_t)t*NH);
    }

    // warp-local wait: only my chunk's producer must have finished step t-1
    if (t > 0) {
      while (ld_acq(myprod) < (unsigned)t) { }
    }

    // stage my 1KB chunk h[8b][k0..k0+32) (bypass L1; written by other SMs)
    {
      const float4* src = (t == 0)
        ? h0s
        : (const float4*)(g_h + (size_t)((t-1)&1)*NBATCH*NH + (size_t)bgrp*8*NH);
      int i0 = sb*128 + r*8 + sc;
      hsm4[i0]     = __ldcg(src + i0);
      hsm4[i0 + 4] = __ldcg(src + i0 + 4);
    }
    __syncwarp();   // my lanes' stores visible to my lanes' loads

    // K-split matvec: k in [r*32, r*32+32), all 3 gates, 8 batches, packed fp32x2
    u64 ar2[8] = {}, az2[8] = {}, an2[8] = {};
    #pragma unroll 2
    for (int kk = 0; kk < 32; kk += 4) {
      int k = k0 + kk;
      ulonglong2 vr = *(const ulonglong2*)(wr + k);
      ulonglong2 vz = *(const ulonglong2*)(wz + k);
      ulonglong2 vn = *(const ulonglong2*)(wn + k);
      #pragma unroll
      for (int b = 0; b < 8; b++) {
        ulonglong2 hv = *(const ulonglong2*)(hsm + b*NH + k);
        FMA2(ar2[b], vr.x, hv.x); FMA2(ar2[b], vr.y, hv.y);
        FMA2(az2[b], vz.x, hv.x); FMA2(az2[b], vz.y, hv.y);
        FMA2(an2[b], vn.x, hv.x); FMA2(an2[b], vn.y, hv.y);
      }
    }

    // horizontal sums
    float sr[8], sz[8], sn[8];
    #pragma unroll
    for (int b = 0; b < 8; b++) {
      float lo, hi;
      UNPACK2(lo, hi, ar2[b]); sr[b] = lo + hi;
      UNPACK2(lo, hi, az2[b]); sz[b] = lo + hi;
      UNPACK2(lo, hi, an2[b]); sn[b] = lo + hi;
    }
    __syncthreads();                                    // B3: all hsm reads done

    // warps 8..15 dump partials into row (r-8)
    if (r >= 8) {
      int row = (r - 8)*768;
      #pragma unroll
      for (int b = 0; b < 8; b++) {
        part[row +   0 + b*32 + jl] = sr[b];
        part[row + 256 + b*32 + jl] = sz[b];
        part[row + 512 + b*32 + jl] = sn[b];
      }
    }
    __syncthreads();                                    // B4

    // warps 0..7 add partner row in place
    if (r < 8) {
      int row = r*768;
      #pragma unroll
      for (int b = 0; b < 8; b++) {
        part[row +   0 + b*32 + jl] += sr[b];
        part[row + 256 + b*32 + jl] += sz[b];
        part[row + 512 + b*32 + jl] += sn[b];
      }
    }
    __syncthreads();                                    // B5

    // epilogue: threads 0..255, thread tid owns (b = tid>>5 == r, column j)
    if (tid < 256) {
      float Sr = 0.f, Sz = 0.f, Sn = 0.f;
      #pragma unroll
      for (int rr = 0; rr < 8; rr++) {
        Sr += part[rr*768 +       tid];
        Sz += part[rr*768 + 256 + tid];
        Sn += part[rr*768 + 512 + tid];
      }
      float rg = 1.f/(1.f + __expf(-(xr + Sr + bhr)));
      float zg = 1.f/(1.f + __expf(-(xz + Sz + bhz)));
      float ng = tanhf(xn + rg*(Sn + bhn));
      float hnew = (1.f - zg)*ng + zg*hprev;
      hprev = hnew;

      __stcs(out_p + (size_t)t*NH, hnew);
      g_h[(size_t)(t&1)*NBATCH*NH + (size_t)bb*NH + j] = hnew;
      if (write_hlast && t == NSTEP-1) hlast_p[0] = hnew;
    }

    // bar.sync + release-store gives happens-before for all h stores
    __syncthreads();                                    // B6
    if (tid == 0) st_rel(myflag, (unsigned)(t+1));
  }
}

extern "C" void kernel_launch(void* const* d_in, const int* in_sizes, int n_in,
                              void* d_out, int out_size) {
  const float* inp  = (const float*)d_in[0];
  const float* h0   = (const float*)d_in[1];
  const float* w_ir = (const float*)d_in[2];
  const float* w_iz = (const float*)d_in[3];
  const float* w_in = (const float*)d_in[4];
  const float* b_ir = (const float*)d_in[5];
  const float* b_iz = (const float*)d_in[6];
  const float* b_in = (const float*)d_in[7];
  const float* w_hr = (const float*)d_in[8];
  const float* w_hz = (const float*)d_in[9];
  const float* w_hn = (const float*)d_in[10];
  const float* b_hr = (const float*)d_in[11];
  const float* b_hz = (const float*)d_in[12];
  const float* b_hn = (const float*)d_in[13];
  float* out = (float*)d_out;

  cudaFuncSetAttribute(gru_rec, cudaFuncAttributeMaxDynamicSharedMemorySize, SMEM_BYTES);

  dim3 gg(NH/64, (NBATCH*NSTEP)/64, 3);
  xproj_kernel<<<gg, 256>>>(inp, w_ir, w_iz, w_in, b_ir, b_iz, b_in);

  int write_hlast = (out_size >= NBATCH*NSTEP*NH + NBATCH*NH) ? 1 : 0;
  gru_rec<<<128, 512, SMEM_BYTES>>>(h0, w_hr, w_hz, w_hn, b_hr, b_hz, b_hn,
                                    out, write_hlast);
}

// round 7
// speedup vs baseline: 1.6350x; 1.6350x over previous
#include <cuda_runtime.h>
#include <math.h>

#define NBATCH 64
#define NSTEP  1024
#define NIN    256
#define NH     512

#define WROW 516  // padded k-stride (floats)
// smem: weights [3][32][WROW] + union(hsm 16KB / part 24KB) + done[16]
#define SMEM_FLOATS (3*32*WROW + 8*768 + 16)
#define SMEM_BYTES  (SMEM_FLOATS*4)

typedef unsigned long long u64;

// packed fp32x2 FMA — SASS FFMA2
#define FMA2(acc, a, b) asm("fma.rn.f32x2 %0, %1, %2, %0;" : "+l"(acc) : "l"(a), "l"(b))
#define DUP2(r, x)      asm("mov.b64 %0, {%1, %1};" : "=l"(r) : "f"(x))
#define UNPACK2(lo, hi, v) asm("mov.b64 {%0, %1}, %2;" : "=f"(lo), "=f"(hi) : "l"(v))

__device__ float    g_x[(size_t)3*NBATCH*NSTEP*NH];   // ~403 MB
__device__ float    g_h[2*NBATCH*NH];
__device__ unsigned g_flags[128];

__device__ __forceinline__ unsigned ld_acq(const unsigned* p) {
  unsigned v;
  asm volatile("ld.global.acquire.gpu.b32 %0, [%1];" : "=r"(v) : "l"(p) : "memory");
  return v;
}
__device__ __forceinline__ void st_rel(unsigned* p, unsigned v) {
  asm volatile("st.global.release.gpu.b32 [%0], %1;" :: "l"(p), "r"(v) : "memory");
}
// local (cta-scope) acquire/release on shared memory via generic pointers
__device__ __forceinline__ unsigned ld_acq_sh(const unsigned* p) {
  unsigned v;
  asm volatile("ld.acquire.cta.b32 %0, [%1];" : "=r"(v) : "l"(p) : "memory");
  return v;
}
__device__ __forceinline__ void st_rel_sh(unsigned* p, unsigned v) {
  asm volatile("st.release.cta.b32 [%0], %1;" :: "l"(p), "r"(v) : "memory");
}

// ---------------- input projection GEMM ----------------
__global__ void __launch_bounds__(256) xproj_kernel(
    const float* __restrict__ A,
    const float* __restrict__ w0, const float* __restrict__ w1, const float* __restrict__ w2,
    const float* __restrict__ b0, const float* __restrict__ b1, const float* __restrict__ b2)
{
  __shared__ float As[32][68];
  __shared__ float Bs[32][68];

  int tid = threadIdx.x;
  if (blockIdx.x == 0 && blockIdx.y == 0 && blockIdx.z == 0 && tid < 128)
    g_flags[tid] = 0u;

  int g = blockIdx.z;
  const float* W    = (g==0) ? w0 : ((g==1) ? w1 : w2);
  const float* bias = (g==0) ? b0 : ((g==1) ? b1 : b2);
  float* C = g_x + (size_t)g * (size_t)(NBATCH*NSTEP) * NH;

  int m0 = blockIdx.y * 64;
  int n0 = blockIdx.x * 64;
  int tx = tid & 15, ty = tid >> 4;
  int lr = tid >> 3;
  int lc = (tid & 7) * 4;

  u64 acc2[4][2] = {};

  for (int k0 = 0; k0 < NIN; k0 += 32) {
    float4 a0 = *(const float4*)(A + (size_t)(m0+lr   )*NIN + k0 + lc);
    float4 a1 = *(const float4*)(A + (size_t)(m0+lr+32)*NIN + k0 + lc);
    float4 v0 = *(const float4*)(W + (size_t)(n0+lr   )*NIN + k0 + lc);
    float4 v1 = *(const float4*)(W + (size_t)(n0+lr+32)*NIN + k0 + lc);
    __syncthreads();
    As[lc+0][lr] = a0.x; As[lc+1][lr] = a0.y; As[lc+2][lr] = a0.z; As[lc+3][lr] = a0.w;
    As[lc+0][lr+32] = a1.x; As[lc+1][lr+32] = a1.y; As[lc+2][lr+32] = a1.z; As[lc+3][lr+32] = a1.w;
    Bs[lc+0][lr] = v0.x; Bs[lc+1][lr] = v0.y; Bs[lc+2][lr] = v0.z; Bs[lc+3][lr] = v0.w;
    Bs[lc+0][lr+32] = v1.x; Bs[lc+1][lr+32] = v1.y; Bs[lc+2][lr+32] = v1.z; Bs[lc+3][lr+32] = v1.w;
    __syncthreads();
    #pragma unroll
    for (int kk = 0; kk < 32; kk++) {
      float4 av = *(const float4*)(&As[kk][ty*4]);
      ulonglong2 bp = *(const ulonglong2*)(&Bs[kk][tx*4]);
      u64 d0, d1, d2, d3;
      DUP2(d0, av.x); DUP2(d1, av.y); DUP2(d2, av.z); DUP2(d3, av.w);
      FMA2(acc2[0][0], d0, bp.x); FMA2(acc2[0][1], d0, bp.y);
      FMA2(acc2[1][0], d1, bp.x); FMA2(acc2[1][1], d1, bp.y);
      FMA2(acc2[2][0], d2, bp.x); FMA2(acc2[2][1], d2, bp.y);
      FMA2(acc2[3][0], d3, bp.x); FMA2(acc2[3][1], d3, bp.y);
    }
  }

  float4 bv = *(const float4*)(bias + n0 + tx*4);
  #pragma unroll
  for (int i = 0; i < 4; i++) {
    int row = m0 + ty*4 + i;
    float c0, c1, c2, c3;
    UNPACK2(c0, c1, acc2[i][0]);
    UNPACK2(c2, c3, acc2[i][1]);
    float4 o;
    o.x = c0 + bv.x; o.y = c1 + bv.y;
    o.z = c2 + bv.z; o.w = c3 + bv.w;
    *(float4*)(C + (size_t)row*NH + n0 + tx*4) = o;
  }
}

// ---------------- persistent GRU recurrence ----------------
// 128 CTAs: blockIdx = bgrp(8)*16 + jt(16). 544 threads:
//   warps 0..15 : workers (k-split 16, 32 k's each; jl = lane = j column)
//   warp  16    : L2 flag poller -> republishes into local smem done[16]
// Worker warp r spins on LOCAL done[r] (broadcast LDS), stages its own 1KB h-chunk
// via __ldcg, runs its matvec slice as soon as its chunk is ready. Named barrier 1
// (512 worker threads) for the reduce phases; poller never joins it.
__global__ void __launch_bounds__(544, 1) gru_rec(
    const float* __restrict__ h0,
    const float* __restrict__ w_hr, const float* __restrict__ w_hz, const float* __restrict__ w_hn,
    const float* __restrict__ b_hr, const float* __restrict__ b_hz, const float* __restrict__ b_hn,
    float* __restrict__ out, int write_hlast)
{
  extern __shared__ float sm[];
  float* wsm  = sm;                          // [3][32][WROW]
  float* un   = sm + 3*32*WROW;              // union: hsm [8][512] / part [8][768]
  float* hsm  = un;
  float* part = un;
  unsigned* done = (unsigned*)(sm + 3*32*WROW + 8*768);  // [16]

  int tid  = threadIdx.x;
  int r    = tid >> 5;                 // worker: 0..15 k-split; 16 = poller warp
  int jl   = tid & 31;
  int bgrp = blockIdx.x >> 4;
  int jt   = blockIdx.x & 15;
  int j    = jt*32 + jl;
  int k0   = r*32;

  float bhr = 0.f, bhz = 0.f, bhn = 0.f, hprev = 0.f;
  int bb = bgrp*8 + r;                 // epilogue batch (valid r<8)

  if (tid < 512) {
    // load recurrent weights for this j-slice into smem: wsm[g][jl][k]
    const float* srcs[3] = {w_hr, w_hz, w_hn};
    #pragma unroll
    for (int g = 0; g < 3; g++) {
      const float* wsrc = srcs[g] + (size_t)j*NH;
      float* wdst = wsm + (g*32 + jl)*WROW;
      #pragma unroll
      for (int kk = 0; kk < 32; kk += 4)
        *(float4*)(wdst + k0 + kk) = *(const float4*)(wsrc + k0 + kk);
    }
    bhr = b_hr[j]; bhz = b_hz[j]; bhn = b_hn[j];
    if (r < 8) hprev = h0[(size_t)bb*NH + j];
  }
  if (tid < 16) done[tid] = 0u;

  __syncthreads();   // all 544: weights + done[] visible

  // ---- poller warp ----
  if (tid >= 512) {
    int lane = tid - 512;
    if (lane < 16) {
      const unsigned* fp = g_flags + bgrp*16 + lane;
      unsigned* dp = done + lane;
      unsigned last = 0u;
      while (last < (unsigned)NSTEP) {
        unsigned v = ld_acq(fp);
        if (v > last) { last = v; st_rel_sh(dp, v); }
        else __nanosleep(40);
      }
    }
    return;
  }

  // ---- workers ----
  const float* xr_p = g_x + (size_t)bb*NSTEP*NH + j;
  const float* xz_p = xr_p + (size_t)NBATCH*NSTEP*NH;
  const float* xn_p = xz_p + (size_t)NBATCH*NSTEP*NH;
  float* out_p   = out + (size_t)bb*NSTEP*NH + j;
  float* hlast_p = out + (size_t)NBATCH*NSTEP*NH + (size_t)bb*NH + j;

  unsigned* myflag = g_flags + bgrp*16 + jt;

  const float* wr = wsm + (0*32 + jl)*WROW;
  const float* wz = wsm + (1*32 + jl)*WROW;
  const float* wn = wsm + (2*32 + jl)*WROW;

  // staging map: warp r stages its 1KB chunk h[8b][k0..k0+32)
  int sb = jl >> 2;                    // batch 0..7
  int sc = jl & 3;                     // float4 sub-index
  const float4* h0s = (const float4*)(h0 + (size_t)bgrp*8*NH);
  float4* hsm4 = (float4*)hsm;

  #pragma unroll 1
  for (int t = 0; t < NSTEP; t++) {
    // prefetch x (epilogue threads)
    float xr = 0.f, xz = 0.f, xn = 0.f;
    if (r < 8) {
      xr = __ldcs(xr_p + (size_t)t*NH);
      xz = __ldcs(xz_p + (size_t)t*NH);
      xn = __ldcs(xn_p + (size_t)t*NH);
    }

    // per-warp wait on LOCAL done flag for my source chunk
    if (t > 0) {
      if (ld_acq_sh(done + r) < (unsigned)t) {
        while (ld_acq_sh(done + r) < (unsigned)t) __nanosleep(20);
      }
    }

    // stage my chunk (L2 pull, bypass L1)
    {
      const float4* src = (t == 0)
        ? h0s
        : (const float4*)(g_h + (size_t)((t-1)&1)*NBATCH*NH + (size_t)bgrp*8*NH);
      int i0 = sb*128 + r*8 + sc;
      hsm4[i0]     = __ldcg(src + i0);
      hsm4[i0 + 4] = __ldcg(src + i0 + 4);
    }
    __syncwarp();

    // K-split matvec: k in [r*32, r*32+32), 3 gates, 8 batches, packed fp32x2
    u64 ar2[8] = {}, az2[8] = {}, an2[8] = {};
    #pragma unroll 2
    for (int kk = 0; kk < 32; kk += 4) {
      int k = k0 + kk;
      ulonglong2 vr = *(const ulonglong2*)(wr + k);
      ulonglong2 vz = *(const ulonglong2*)(wz + k);
      ulonglong2 vn = *(const ulonglong2*)(wn + k);
      #pragma unroll
      for (int b = 0; b < 8; b++) {
        ulonglong2 hv = *(const ulonglong2*)(hsm + b*NH + k);
        FMA2(ar2[b], vr.x, hv.x); FMA2(ar2[b], vr.y, hv.y);
        FMA2(az2[b], vz.x, hv.x); FMA2(az2[b], vz.y, hv.y);
        FMA2(an2[b], vn.x, hv.x); FMA2(an2[b], vn.y, hv.y);
      }
    }

    float sr[8], sz[8], sn[8];
    #pragma unroll
    for (int b = 0; b < 8; b++) {
      float lo, hi;
      UNPACK2(lo, hi, ar2[b]); sr[b] = lo + hi;
      UNPACK2(lo, hi, az2[b]); sz[b] = lo + hi;
      UNPACK2(lo, hi, an2[b]); sn[b] = lo + hi;
    }
    asm volatile("bar.sync 1, 512;" ::: "memory");      // B3: all hsm reads done

    if (r >= 8) {
      int row = (r - 8)*768;
      #pragma unroll
      for (int b = 0; b < 8; b++) {
        part[row +   0 + b*32 + jl] = sr[b];
        part[row + 256 + b*32 + jl] = sz[b];
        part[row + 512 + b*32 + jl] = sn[b];
      }
    }
    asm volatile("bar.sync 1, 512;" ::: "memory");      // B4

    if (r < 8) {
      int row = r*768;
      #pragma unroll
      for (int b = 0; b < 8; b++) {
        part[row +   0 + b*32 + jl] += sr[b];
        part[row + 256 + b*32 + jl] += sz[b];
        part[row + 512 + b*32 + jl] += sn[b];
      }
    }
    asm volatile("bar.sync 1, 512;" ::: "memory");      // B5

    if (tid < 256) {
      float Sr = 0.f, Sz = 0.f, Sn = 0.f;
      #pragma unroll
      for (int rr = 0; rr < 8; rr++) {
        Sr += part[rr*768 +       tid];
        Sz += part[rr*768 + 256 + tid];
        Sn += part[rr*768 + 512 + tid];
      }
      float rg = 1.f/(1.f + __expf(-(xr + Sr + bhr)));
      float zg = 1.f/(1.f + __expf(-(xz + Sz + bhz)));
      float ng = tanhf(xn + rg*(Sn + bhn));
      float hnew = (1.f - zg)*ng + zg*hprev;
      hprev = hnew;

      __stcs(out_p + (size_t)t*NH, hnew);
      __stcg(&g_h[(size_t)(t&1)*NBATCH*NH + (size_t)bb*NH + j], hnew);
      if (write_hlast && t == NSTEP-1) hlast_p[0] = hnew;

      // early release: only epilogue threads' stores matter for h(t)
      asm volatile("bar.sync 2, 256;" ::: "memory");
      if (tid == 0) {
        st_rel(myflag, (unsigned)(t+1));
        st_rel_sh(done + jt, (unsigned)(t+1));   // self-publish, skip L2 trip
      }
    }

    asm volatile("bar.sync 1, 512;" ::: "memory");      // B6: before hsm overlay reuse
  }
}

extern "C" void kernel_launch(void* const* d_in, const int* in_sizes, int n_in,
                              void* d_out, int out_size) {
  const float* inp  = (const float*)d_in[0];
  const float* h0   = (const float*)d_in[1];
  const float* w_ir = (const float*)d_in[2];
  const float* w_iz = (const float*)d_in[3];
  const float* w_in = (const float*)d_in[4];
  const float* b_ir = (const float*)d_in[5];
  const float* b_iz = (const float*)d_in[6];
  const float* b_in = (const float*)d_in[7];
  const float* w_hr = (const float*)d_in[8];
  const float* w_hz = (const float*)d_in[9];
  const float* w_hn = (const float*)d_in[10];
  const float* b_hr = (const float*)d_in[11];
  const float* b_hz = (const float*)d_in[12];
  const float* b_hn = (const float*)d_in[13];
  float* out = (float*)d_out;

  cudaFuncSetAttribute(gru_rec, cudaFuncAttributeMaxDynamicSharedMemorySize, SMEM_BYTES);

  dim3 gg(NH/64, (NBATCH*NSTEP)/64, 3);
  xproj_kernel<<<gg, 256>>>(inp, w_ir, w_iz, w_in, b_ir, b_iz, b_in);

  int write_hlast = (out_size >= NBATCH*NSTEP*NH + NBATCH*NH) ? 1 : 0;
  gru_rec<<<128, 544, SMEM_BYTES>>>(h0, w_hr, w_hz, w_hn, b_hr, b_hz, b_hn,
                                    out, write_hlast);
}